// round 11
// baseline (speedup 1.0000x reference)
#include <cuda_runtime.h>
#include <cuda_bf16.h>
#include <stdint.h>
#include <math.h>

// Problem constants
#define BB 2
#define SS 2048
#define DD 2048
#define HH 16
#define HDD 128
#define NDD 64
#define RR 512

// ---------------------------------------------------------------------------
// Scratch (device globals: no allocations allowed)
// ---------------------------------------------------------------------------
__device__ float g_qfull[BB * SS * DD];
__device__ float g_ckv[BB * SS * RR];
__device__ float g_knope[BB * SS * HH * NDD];
__device__ float g_krope[BB * SS * 64];
__device__ float g_vflat[BB * SS * DD];
__device__ float g_Q[BB * HH * SS * HDD];
__device__ float g_K[BB * HH * SS * HDD];
__device__ float g_attn[BB * SS * DD];

// bf16 hi/lo split buffers
__device__ __nv_bfloat16 g_xh[BB * SS * DD],  g_xl[BB * SS * DD];
__device__ __nv_bfloat16 g_wqh[DD * DD],      g_wql[DD * DD];
__device__ __nv_bfloat16 g_wkvh[RR * DD],     g_wkvl[RR * DD];
__device__ __nv_bfloat16 g_wkuph[HH * NDD * RR], g_wkupl[HH * NDD * RR];
__device__ __nv_bfloat16 g_wkrh[64 * DD],     g_wkrl[64 * DD];
__device__ __nv_bfloat16 g_wvuph[DD * RR],    g_wvupl[DD * RR];
__device__ __nv_bfloat16 g_woh[DD * DD],      g_wol[DD * DD];
__device__ __nv_bfloat16 g_ckvh[BB * SS * RR], g_ckvl[BB * SS * RR];
__device__ __nv_bfloat16 g_ath[BB * SS * DD],  g_atl[BB * SS * DD];

__constant__ float c_freqs[32] = {
    1.0f, 0.7498942093324559f, 0.5623413251903491f, 0.42169650342858224f,
    0.31622776601683794f, 0.23713737056616552f, 0.17782794100389228f, 0.13335214321633237f,
    0.1f, 0.07498942093324558f, 0.05623413251903491f, 0.042169650342858224f,
    0.03162277660168379f, 0.023713737056616554f, 0.01778279410038923f, 0.013335214321633237f,
    0.01f, 0.007498942093324559f, 0.005623413251903491f, 0.004216965034285822f,
    0.0031622776601683794f, 0.0023713737056616554f, 0.0017782794100389228f, 0.0013335214321633237f,
    0.001f, 0.0007498942093324559f, 0.0005623413251903491f, 0.00042169650342858224f,
    0.00031622776601683794f, 0.00023713737056616554f, 0.00017782794100389228f, 0.00013335214321633237f};

// ---------------------------------------------------------------------------
// PTX helpers (sm_80-era ISA only — tcgen05 is NOT available: harness ptxas
// target is sm_103 without the 'a' feature suffix)
// ---------------------------------------------------------------------------
__device__ __forceinline__ uint32_t smem_u32(const void* p) {
    uint32_t a;
    asm("{ .reg .u64 t; cvta.to.shared.u64 t, %1; cvt.u32.u64 %0, t; }" : "=r"(a) : "l"(p));
    return a;
}
__device__ __forceinline__ uint32_t sw128(uint32_t o) { return o ^ ((o >> 3) & 0x70); }

__device__ __forceinline__ void cp16(uint32_t smem_dst, const void* gsrc) {
    asm volatile("cp.async.cg.shared.global [%0], [%1], 16;" :: "r"(smem_dst), "l"(gsrc));
}
__device__ __forceinline__ void cp16z(uint32_t smem_dst, const void* gsrc, bool valid) {
    int sz = valid ? 16 : 0;
    asm volatile("cp.async.cg.shared.global [%0], [%1], 16, %2;"
                 :: "r"(smem_dst), "l"(gsrc), "r"(sz));
}
__device__ __forceinline__ void ldsm4(uint32_t* r, uint32_t addr) {
    asm volatile("ldmatrix.sync.aligned.m8n8.x4.shared.b16 {%0,%1,%2,%3}, [%4];"
                 : "=r"(r[0]), "=r"(r[1]), "=r"(r[2]), "=r"(r[3]) : "r"(addr));
}
__device__ __forceinline__ void ldsm2(uint32_t* r, uint32_t addr) {
    asm volatile("ldmatrix.sync.aligned.m8n8.x2.shared.b16 {%0,%1}, [%2];"
                 : "=r"(r[0]), "=r"(r[1]) : "r"(addr));
}
__device__ __forceinline__ void mma16816(float* c, const uint32_t* a, const uint32_t* b) {
    asm volatile(
        "mma.sync.aligned.m16n8k16.row.col.f32.bf16.bf16.f32 "
        "{%0,%1,%2,%3}, {%4,%5,%6,%7}, {%8,%9}, {%0,%1,%2,%3};"
        : "+f"(c[0]), "+f"(c[1]), "+f"(c[2]), "+f"(c[3])
        : "r"(a[0]), "r"(a[1]), "r"(a[2]), "r"(a[3]), "r"(b[0]), "r"(b[1]));
}

// ---------------------------------------------------------------------------
// split fp32 -> bf16 hi + bf16 lo
// ---------------------------------------------------------------------------
__global__ void split_kernel(const float4* __restrict__ s, __nv_bfloat162* __restrict__ h,
                             __nv_bfloat162* __restrict__ l, int n4) {
    int i = blockIdx.x * blockDim.x + threadIdx.x;
    if (i >= n4) return;
    float4 v = s[i];
    __nv_bfloat16 hx = __float2bfloat16(v.x), hy = __float2bfloat16(v.y);
    __nv_bfloat16 hz = __float2bfloat16(v.z), hw = __float2bfloat16(v.w);
    __nv_bfloat16 lx = __float2bfloat16(v.x - __bfloat162float(hx));
    __nv_bfloat16 ly = __float2bfloat16(v.y - __bfloat162float(hy));
    __nv_bfloat16 lz = __float2bfloat16(v.z - __bfloat162float(hz));
    __nv_bfloat16 lw = __float2bfloat16(v.w - __bfloat162float(hw));
    h[2 * i]     = __nv_bfloat162(hx, hy);
    h[2 * i + 1] = __nv_bfloat162(hz, hw);
    l[2 * i]     = __nv_bfloat162(lx, ly);
    l[2 * i + 1] = __nv_bfloat162(lz, lw);
}

// ---------------------------------------------------------------------------
// 3-pass bf16 mma.sync GEMM: C[M,N] = A[M,K] @ B[N,K]^T, fp32 out.
// CTA tile 128x128, BK=64, double-buffered cp.async, SW128 swizzle.
// 256 threads = 8 warps (2 x 4); warp tile 64 x 32.
// Requires M%128==0, K%64==0. N handled with zero-fill + store guards.
// ---------------------------------------------------------------------------
#define GEMM_SMEM (2 * 4 * 128 * 128)

__global__ __launch_bounds__(256) void gemm3m(
    const __nv_bfloat16* __restrict__ Ah, const __nv_bfloat16* __restrict__ Al,
    const __nv_bfloat16* __restrict__ Bh, const __nv_bfloat16* __restrict__ Bl,
    float* __restrict__ C, int M, int N, int K) {
    extern __shared__ __align__(1024) char smem[];
    const uint32_t sb = smem_u32(smem);
    const int tid = threadIdx.x;
    const int lane = tid & 31;
    const int wid = tid >> 5;
    const int wr = wid >> 2, wc = wid & 3;
    const int m0 = blockIdx.y * 128, n0 = blockIdx.x * 128;

    constexpr int TILE = 128 * 128;        // bytes per operand tile
    constexpr int STAGE = 4 * TILE;        // Ah, Al, Bh, Bl

    const int nk = K >> 6;

    auto load_stage = [&](int kc, int s) {
        uint32_t base = sb + s * STAGE;
        int k0 = kc * 64;
        for (int e = tid; e < 4096; e += 256) {
            int t = e >> 10, r = (e >> 3) & 127, c = e & 7;
            uint32_t dst = base + t * TILE + sw128((uint32_t)(r * 128 + c * 16));
            if (t == 0) {
                cp16(dst, Ah + (size_t)(m0 + r) * K + k0 + c * 8);
            } else if (t == 1) {
                cp16(dst, Al + (size_t)(m0 + r) * K + k0 + c * 8);
            } else if (t == 2) {
                bool v = (n0 + r) < N;
                cp16z(dst, Bh + (size_t)(v ? (n0 + r) : 0) * K + k0 + c * 8, v);
            } else {
                bool v = (n0 + r) < N;
                cp16z(dst, Bl + (size_t)(v ? (n0 + r) : 0) * K + k0 + c * 8, v);
            }
        }
        asm volatile("cp.async.commit_group;" ::: "memory");
    };

    float acc[4][4][4];
#pragma unroll
    for (int mi = 0; mi < 4; mi++)
#pragma unroll
        for (int ni = 0; ni < 4; ni++)
#pragma unroll
            for (int j = 0; j < 4; j++) acc[mi][ni][j] = 0.0f;

    load_stage(0, 0);

    const int l16 = lane & 15;
    for (int kc = 0; kc < nk; kc++) {
        if (kc + 1 < nk) {
            load_stage(kc + 1, (kc + 1) & 1);
            asm volatile("cp.async.wait_group 1;" ::: "memory");
        } else {
            asm volatile("cp.async.wait_group 0;" ::: "memory");
        }
        __syncthreads();

        uint32_t base = sb + (kc & 1) * STAGE;
#pragma unroll
        for (int s = 0; s < 4; s++) {
            const int ksb = s * 32;  // k16 step -> bytes within row
            // A fragments (hi & lo)
            uint32_t ah[4][4], al[4][4];
            uint32_t aintra = (uint32_t)(ksb + (lane >> 4) * 16);
#pragma unroll
            for (int mi = 0; mi < 4; mi++) {
                uint32_t off = (uint32_t)((wr * 64 + mi * 16 + l16) * 128) + aintra;
                ldsm4(ah[mi], base + 0 * TILE + sw128(off));
                ldsm4(al[mi], base + 1 * TILE + sw128(off));
            }
            // B fragments (hi & lo)
            uint32_t bh[4][2], bl[4][2];
            uint32_t bintra = (uint32_t)(ksb + (l16 >> 3) * 16);
#pragma unroll
            for (int ni = 0; ni < 4; ni++) {
                uint32_t off = (uint32_t)((wc * 32 + ni * 8 + (l16 & 7)) * 128) + bintra;
                ldsm2(bh[ni], base + 2 * TILE + sw128(off));
                ldsm2(bl[ni], base + 3 * TILE + sw128(off));
            }
#pragma unroll
            for (int mi = 0; mi < 4; mi++)
#pragma unroll
                for (int ni = 0; ni < 4; ni++) {
                    mma16816(acc[mi][ni], ah[mi], bh[ni]);
                    mma16816(acc[mi][ni], ah[mi], bl[ni]);
                    mma16816(acc[mi][ni], al[mi], bh[ni]);
                }
        }
        __syncthreads();
    }

    // epilogue
#pragma unroll
    for (int mi = 0; mi < 4; mi++) {
        int row = m0 + wr * 64 + mi * 16 + (lane >> 2);
#pragma unroll
        for (int ni = 0; ni < 4; ni++) {
            int col = n0 + wc * 32 + ni * 8 + (lane & 3) * 2;
            if (col < N) {
                *(float2*)&C[(size_t)row * N + col] = make_float2(acc[mi][ni][0], acc[mi][ni][1]);
                *(float2*)&C[(size_t)(row + 8) * N + col] = make_float2(acc[mi][ni][2], acc[mi][ni][3]);
            }
        }
    }
}

// ---------------------------------------------------------------------------
// Pack Q / K
// ---------------------------------------------------------------------------
__global__ void pack_q_kernel(const float* __restrict__ qfull, float* __restrict__ Q) {
    long idx = (long)blockIdx.x * blockDim.x + threadIdx.x;
    int i = (int)(idx & 63);
    long t = idx >> 6;
    int s = (int)(t & (SS - 1));
    t >>= 11;
    int h = (int)(t & (HH - 1));
    int b = (int)(t >> 4);
    const float scale = 0.08838834764831845f;
    const float* src = qfull + ((size_t)(b * SS + s)) * DD + h * HDD;
    float* dst = Q + (((size_t)(b * HH + h) * SS + s)) * HDD;
    if (i < 32) {
        dst[2 * i]     = src[2 * i] * scale;
        dst[2 * i + 1] = src[2 * i + 1] * scale;
    } else {
        int j = i - 32;
        float x0 = src[64 + 2 * j], x1 = src[64 + 2 * j + 1];
        float ang = (float)s * c_freqs[j];
        float sn, cs;
        sincosf(ang, &sn, &cs);
        dst[64 + 2 * j]     = (x0 * cs - x1 * sn) * scale;
        dst[64 + 2 * j + 1] = (x1 * cs + x0 * sn) * scale;
    }
}

__global__ void pack_k_kernel(const float* __restrict__ knope,
                              const float* __restrict__ krope,
                              float* __restrict__ K) {
    long idx = (long)blockIdx.x * blockDim.x + threadIdx.x;
    int i = (int)(idx & 63);
    long t = idx >> 6;
    int s = (int)(t & (SS - 1));
    t >>= 11;
    int h = (int)(t & (HH - 1));
    int b = (int)(t >> 4);
    float* dst = K + (((size_t)(b * HH + h) * SS + s)) * HDD;
    if (i < 32) {
        const float* src = knope + ((size_t)(b * SS + s)) * (HH * NDD) + h * NDD;
        dst[2 * i]     = src[2 * i];
        dst[2 * i + 1] = src[2 * i + 1];
    } else {
        int j = i - 32;
        const float* src = krope + ((size_t)(b * SS + s)) * 64;
        float x0 = src[2 * j], x1 = src[2 * j + 1];
        float ang = (float)s * c_freqs[j];
        float sn, cs;
        sincosf(ang, &sn, &cs);
        dst[64 + 2 * j]     = x0 * cs - x1 * sn;
        dst[64 + 2 * j + 1] = x1 * cs + x0 * sn;
    }
}

// ---------------------------------------------------------------------------
// Flash attention (fp32, causal) — unchanged
// ---------------------------------------------------------------------------
#define FA_SMEM ((3 * 64 * 132 + 64 * 68) * 4)

__global__ __launch_bounds__(256) void fa_kernel(const float* __restrict__ Qp,
                                                 const float* __restrict__ Kp,
                                                 const float* __restrict__ Vf,
                                                 float* __restrict__ Oo) {
    extern __shared__ float sm[];
    float* Qs = sm;
    float* Ks = Qs + 64 * 132;
    float* Vs = Ks + 64 * 132;
    float* Ps = Vs + 64 * 132;

    const int tid = threadIdx.x;
    const int tx = tid & 15, ty = tid >> 4;
    const int bh = blockIdx.y;
    const int b = bh >> 4, h = bh & 15;
    const int qt = blockIdx.x;
    const int q0 = qt * 64;

    const float* Qbase = Qp + ((size_t)bh * SS + q0) * HDD;
    for (int e = tid; e < 64 * 32; e += 256) {
        int r = e >> 5, c4 = (e & 31) << 2;
        *(float4*)(Qs + r * 132 + c4) = *(const float4*)(Qbase + r * HDD + c4);
    }

    float m_i[4], l_i[4], O[4][8];
#pragma unroll
    for (int i = 0; i < 4; i++) {
        m_i[i] = -1e30f;
        l_i[i] = 0.0f;
#pragma unroll
        for (int j = 0; j < 8; j++) O[i][j] = 0.0f;
    }

    for (int nt = 0; nt <= qt; nt++) {
        const int n0 = nt * 64;
        const float* Kbase = Kp + ((size_t)bh * SS + n0) * HDD;
        for (int e = tid; e < 64 * 32; e += 256) {
            int r = e >> 5, c4 = (e & 31) << 2;
            *(float4*)(Ks + r * 132 + c4) = *(const float4*)(Kbase + r * HDD + c4);
            *(float4*)(Vs + r * 132 + c4) =
                *(const float4*)(Vf + ((size_t)(b * SS + n0 + r)) * DD + h * HDD + c4);
        }
        __syncthreads();

        float acc[4][4];
#pragma unroll
        for (int i = 0; i < 4; i++)
#pragma unroll
            for (int j = 0; j < 4; j++) acc[i][j] = 0.0f;

        for (int d4 = 0; d4 < 32; d4++) {
            float4 q4[4], k4[4];
#pragma unroll
            for (int i = 0; i < 4; i++) q4[i] = *(const float4*)(Qs + (ty * 4 + i) * 132 + d4 * 4);
#pragma unroll
            for (int j = 0; j < 4; j++) k4[j] = *(const float4*)(Ks + (tx + 16 * j) * 132 + d4 * 4);
#pragma unroll
            for (int i = 0; i < 4; i++)
#pragma unroll
                for (int j = 0; j < 4; j++) {
                    acc[i][j] = fmaf(q4[i].x, k4[j].x, acc[i][j]);
                    acc[i][j] = fmaf(q4[i].y, k4[j].y, acc[i][j]);
                    acc[i][j] = fmaf(q4[i].z, k4[j].z, acc[i][j]);
                    acc[i][j] = fmaf(q4[i].w, k4[j].w, acc[i][j]);
                }
        }

        if (nt == qt) {
#pragma unroll
            for (int i = 0; i < 4; i++)
#pragma unroll
                for (int j = 0; j < 4; j++)
                    if (n0 + tx + 16 * j > q0 + ty * 4 + i) acc[i][j] = -1e30f;
        }

#pragma unroll
        for (int i = 0; i < 4; i++) {
            float mx = fmaxf(fmaxf(acc[i][0], acc[i][1]), fmaxf(acc[i][2], acc[i][3]));
#pragma unroll
            for (int o = 8; o >= 1; o >>= 1) mx = fmaxf(mx, __shfl_xor_sync(0xffffffffu, mx, o, 16));
            float mnew = fmaxf(m_i[i], mx);
            float corr = __expf(m_i[i] - mnew);
            float rs = 0.0f;
#pragma unroll
            for (int j = 0; j < 4; j++) {
                float p = __expf(acc[i][j] - mnew);
                acc[i][j] = p;
                rs += p;
            }
#pragma unroll
            for (int o = 8; o >= 1; o >>= 1) rs += __shfl_xor_sync(0xffffffffu, rs, o, 16);
            l_i[i] = l_i[i] * corr + rs;
            m_i[i] = mnew;
#pragma unroll
            for (int j = 0; j < 8; j++) O[i][j] *= corr;
#pragma unroll
            for (int j = 0; j < 4; j++) Ps[(ty * 4 + i) * 68 + tx + 16 * j] = acc[i][j];
        }
        __syncthreads();

        for (int c = 0; c < 64; c++) {
            float p0 = Ps[(ty * 4 + 0) * 68 + c];
            float p1 = Ps[(ty * 4 + 1) * 68 + c];
            float p2 = Ps[(ty * 4 + 2) * 68 + c];
            float p3 = Ps[(ty * 4 + 3) * 68 + c];
            float4 v0 = *(const float4*)(Vs + c * 132 + tx * 8);
            float4 v1 = *(const float4*)(Vs + c * 132 + tx * 8 + 4);
            float vv[8] = {v0.x, v0.y, v0.z, v0.w, v1.x, v1.y, v1.z, v1.w};
#pragma unroll
            for (int j = 0; j < 8; j++) {
                O[0][j] = fmaf(p0, vv[j], O[0][j]);
                O[1][j] = fmaf(p1, vv[j], O[1][j]);
                O[2][j] = fmaf(p2, vv[j], O[2][j]);
                O[3][j] = fmaf(p3, vv[j], O[3][j]);
            }
        }
        __syncthreads();
    }

#pragma unroll
    for (int i = 0; i < 4; i++) {
        float inv = 1.0f / l_i[i];
        int row = q0 + ty * 4 + i;
        float* dst = Oo + ((size_t)(b * SS + row)) * DD + h * HDD + tx * 8;
        *(float4*)(dst)     = make_float4(O[i][0] * inv, O[i][1] * inv, O[i][2] * inv, O[i][3] * inv);
        *(float4*)(dst + 4) = make_float4(O[i][4] * inv, O[i][5] * inv, O[i][6] * inv, O[i][7] * inv);
    }
}

// ---------------------------------------------------------------------------
// Launch
// ---------------------------------------------------------------------------
static void run_split(const float* s, __nv_bfloat16* h, __nv_bfloat16* l, int n) {
    int n4 = n / 4;
    split_kernel<<<(n4 + 255) / 256, 256>>>((const float4*)s, (__nv_bfloat162*)h,
                                            (__nv_bfloat162*)l, n4);
}

extern "C" void kernel_launch(void* const* d_in, const int* in_sizes, int n_in,
                              void* d_out, int out_size) {
    const float* x         = (const float*)d_in[0];
    const float* wq        = (const float*)d_in[1];
    const float* w_kv_down = (const float*)d_in[2];
    const float* w_k_up    = (const float*)d_in[3];
    const float* w_k_rope  = (const float*)d_in[4];
    const float* w_v_up    = (const float*)d_in[5];
    const float* wo        = (const float*)d_in[6];
    float* out = (float*)d_out;

    float *qfull, *ckv, *knope, *krope, *vflat, *Q, *K, *attn;
    cudaGetSymbolAddress((void**)&qfull, g_qfull);
    cudaGetSymbolAddress((void**)&ckv,   g_ckv);
    cudaGetSymbolAddress((void**)&knope, g_knope);
    cudaGetSymbolAddress((void**)&krope, g_krope);
    cudaGetSymbolAddress((void**)&vflat, g_vflat);
    cudaGetSymbolAddress((void**)&Q,     g_Q);
    cudaGetSymbolAddress((void**)&K,     g_K);
    cudaGetSymbolAddress((void**)&attn,  g_attn);

    __nv_bfloat16 *xh, *xl, *wqh, *wql, *wkvh, *wkvl, *wkuph, *wkupl;
    __nv_bfloat16 *wkrh, *wkrl, *wvuph, *wvupl, *woh, *wol, *ckvh, *ckvl, *ath, *atl;
    cudaGetSymbolAddress((void**)&xh, g_xh);       cudaGetSymbolAddress((void**)&xl, g_xl);
    cudaGetSymbolAddress((void**)&wqh, g_wqh);     cudaGetSymbolAddress((void**)&wql, g_wql);
    cudaGetSymbolAddress((void**)&wkvh, g_wkvh);   cudaGetSymbolAddress((void**)&wkvl, g_wkvl);
    cudaGetSymbolAddress((void**)&wkuph, g_wkuph); cudaGetSymbolAddress((void**)&wkupl, g_wkupl);
    cudaGetSymbolAddress((void**)&wkrh, g_wkrh);   cudaGetSymbolAddress((void**)&wkrl, g_wkrl);
    cudaGetSymbolAddress((void**)&wvuph, g_wvuph); cudaGetSymbolAddress((void**)&wvupl, g_wvupl);
    cudaGetSymbolAddress((void**)&woh, g_woh);     cudaGetSymbolAddress((void**)&wol, g_wol);
    cudaGetSymbolAddress((void**)&ckvh, g_ckvh);   cudaGetSymbolAddress((void**)&ckvl, g_ckvl);
    cudaGetSymbolAddress((void**)&ath, g_ath);     cudaGetSymbolAddress((void**)&atl, g_atl);

    cudaFuncSetAttribute(gemm3m, cudaFuncAttributeMaxDynamicSharedMemorySize, GEMM_SMEM);
    cudaFuncSetAttribute(fa_kernel, cudaFuncAttributeMaxDynamicSharedMemorySize, FA_SMEM);

    const int M = BB * SS;  // 4096

    // split inputs + weights
    run_split(x,         xh,    xl,    BB * SS * DD);
    run_split(wq,        wqh,   wql,   DD * DD);
    run_split(w_kv_down, wkvh,  wkvl,  RR * DD);
    run_split(w_k_up,    wkuph, wkupl, HH * NDD * RR);
    run_split(w_k_rope,  wkrh,  wkrl,  64 * DD);
    run_split(w_v_up,    wvuph, wvupl, DD * RR);
    run_split(wo,        woh,   wol,   DD * DD);

    // q = x @ wq^T
    gemm3m<<<dim3(DD / 128, M / 128), 256, GEMM_SMEM>>>(xh, xl, wqh, wql, qfull, M, DD, DD);
    // c_kv = x @ w_kv_down^T
    gemm3m<<<dim3(RR / 128, M / 128), 256, GEMM_SMEM>>>(xh, xl, wkvh, wkvl, ckv, M, RR, DD);
    run_split(ckv, ckvh, ckvl, BB * SS * RR);
    // k_nope = ckv @ w_k_up^T
    gemm3m<<<dim3((HH * NDD) / 128, M / 128), 256, GEMM_SMEM>>>(ckvh, ckvl, wkuph, wkupl,
                                                                knope, M, HH * NDD, RR);
    // k_rope_raw = x @ w_k_rope^T  (N=64 -> zero-fill + guards)
    gemm3m<<<dim3(1, M / 128), 256, GEMM_SMEM>>>(xh, xl, wkrh, wkrl, krope, M, 64, DD);
    // v = ckv @ w_v_up^T
    gemm3m<<<dim3(DD / 128, M / 128), 256, GEMM_SMEM>>>(ckvh, ckvl, wvuph, wvupl, vflat, M, DD, RR);

    pack_q_kernel<<<(BB * HH * SS * 64) / 256, 256>>>(qfull, Q);
    pack_k_kernel<<<(BB * HH * SS * 64) / 256, 256>>>(knope, krope, K);

    fa_kernel<<<dim3(SS / 64, BB * HH), 256, FA_SMEM>>>(Q, K, vflat, attn);

    run_split(attn, ath, atl, BB * SS * DD);
    // out = attn @ wo^T
    gemm3m<<<dim3(DD / 128, M / 128), 256, GEMM_SMEM>>>(ath, atl, woh, wol, out, M, DD, DD);
}

// round 12
// speedup vs baseline: 1.0001x; 1.0001x over previous
#include <cuda_runtime.h>
#include <cuda_bf16.h>
#include <stdint.h>
#include <math.h>

// Problem constants
#define BB 2
#define SS 2048
#define DD 2048
#define HH 16
#define HDD 128
#define NDD 64
#define RR 512

// ---------------------------------------------------------------------------
// Scratch (device globals: no allocations allowed)
// ---------------------------------------------------------------------------
__device__ float g_qfull[BB * SS * DD];
__device__ float g_ckv[BB * SS * RR];
__device__ float g_knope[BB * SS * HH * NDD];
__device__ float g_krope[BB * SS * 64];
__device__ float g_vflat[BB * SS * DD];
__device__ float g_Q[BB * HH * SS * HDD];
__device__ float g_K[BB * HH * SS * HDD];
__device__ float g_attn[BB * SS * DD];

// bf16 hi/lo split buffers
__device__ __nv_bfloat16 g_xh[BB * SS * DD],  g_xl[BB * SS * DD];
__device__ __nv_bfloat16 g_wqh[DD * DD],      g_wql[DD * DD];
__device__ __nv_bfloat16 g_wkvh[RR * DD],     g_wkvl[RR * DD];
__device__ __nv_bfloat16 g_wkuph[HH * NDD * RR], g_wkupl[HH * NDD * RR];
__device__ __nv_bfloat16 g_wkrh[64 * DD],     g_wkrl[64 * DD];
__device__ __nv_bfloat16 g_wvuph[DD * RR],    g_wvupl[DD * RR];
__device__ __nv_bfloat16 g_woh[DD * DD],      g_wol[DD * DD];
__device__ __nv_bfloat16 g_ckvh[BB * SS * RR], g_ckvl[BB * SS * RR];
__device__ __nv_bfloat16 g_ath[BB * SS * DD],  g_atl[BB * SS * DD];

__constant__ float c_freqs[32] = {
    1.0f, 0.7498942093324559f, 0.5623413251903491f, 0.42169650342858224f,
    0.31622776601683794f, 0.23713737056616552f, 0.17782794100389228f, 0.13335214321633237f,
    0.1f, 0.07498942093324558f, 0.05623413251903491f, 0.042169650342858224f,
    0.03162277660168379f, 0.023713737056616554f, 0.01778279410038923f, 0.013335214321633237f,
    0.01f, 0.007498942093324559f, 0.005623413251903491f, 0.004216965034285822f,
    0.0031622776601683794f, 0.0023713737056616554f, 0.0017782794100389228f, 0.0013335214321633237f,
    0.001f, 0.0007498942093324559f, 0.0005623413251903491f, 0.00042169650342858224f,
    0.00031622776601683794f, 0.00023713737056616554f, 0.00017782794100389228f, 0.00013335214321633237f};

// ---------------------------------------------------------------------------
// PTX helpers (sm_80-era ISA only — tcgen05 is NOT available: harness ptxas
// target is sm_103 without the 'a' feature suffix)
// ---------------------------------------------------------------------------
__device__ __forceinline__ uint32_t smem_u32(const void* p) {
    uint32_t a;
    asm("{ .reg .u64 t; cvta.to.shared.u64 t, %1; cvt.u32.u64 %0, t; }" : "=r"(a) : "l"(p));
    return a;
}
__device__ __forceinline__ uint32_t sw128(uint32_t o) { return o ^ ((o >> 3) & 0x70); }

__device__ __forceinline__ void cp16(uint32_t smem_dst, const void* gsrc) {
    asm volatile("cp.async.cg.shared.global [%0], [%1], 16;" :: "r"(smem_dst), "l"(gsrc));
}
__device__ __forceinline__ void cp16z(uint32_t smem_dst, const void* gsrc, bool valid) {
    int sz = valid ? 16 : 0;
    asm volatile("cp.async.cg.shared.global [%0], [%1], 16, %2;"
                 :: "r"(smem_dst), "l"(gsrc), "r"(sz));
}
__device__ __forceinline__ void ldsm4(uint32_t* r, uint32_t addr) {
    asm volatile("ldmatrix.sync.aligned.m8n8.x4.shared.b16 {%0,%1,%2,%3}, [%4];"
                 : "=r"(r[0]), "=r"(r[1]), "=r"(r[2]), "=r"(r[3]) : "r"(addr));
}
__device__ __forceinline__ void ldsm2(uint32_t* r, uint32_t addr) {
    asm volatile("ldmatrix.sync.aligned.m8n8.x2.shared.b16 {%0,%1}, [%2];"
                 : "=r"(r[0]), "=r"(r[1]) : "r"(addr));
}
__device__ __forceinline__ void mma16816(float* c, const uint32_t* a, const uint32_t* b) {
    asm volatile(
        "mma.sync.aligned.m16n8k16.row.col.f32.bf16.bf16.f32 "
        "{%0,%1,%2,%3}, {%4,%5,%6,%7}, {%8,%9}, {%0,%1,%2,%3};"
        : "+f"(c[0]), "+f"(c[1]), "+f"(c[2]), "+f"(c[3])
        : "r"(a[0]), "r"(a[1]), "r"(a[2]), "r"(a[3]), "r"(b[0]), "r"(b[1]));
}

// ---------------------------------------------------------------------------
// split fp32 -> bf16 hi + bf16 lo
// ---------------------------------------------------------------------------
__global__ void split_kernel(const float4* __restrict__ s, __nv_bfloat162* __restrict__ h,
                             __nv_bfloat162* __restrict__ l, int n4) {
    int i = blockIdx.x * blockDim.x + threadIdx.x;
    if (i >= n4) return;
    float4 v = s[i];
    __nv_bfloat16 hx = __float2bfloat16(v.x), hy = __float2bfloat16(v.y);
    __nv_bfloat16 hz = __float2bfloat16(v.z), hw = __float2bfloat16(v.w);
    __nv_bfloat16 lx = __float2bfloat16(v.x - __bfloat162float(hx));
    __nv_bfloat16 ly = __float2bfloat16(v.y - __bfloat162float(hy));
    __nv_bfloat16 lz = __float2bfloat16(v.z - __bfloat162float(hz));
    __nv_bfloat16 lw = __float2bfloat16(v.w - __bfloat162float(hw));
    h[2 * i]     = __nv_bfloat162(hx, hy);
    h[2 * i + 1] = __nv_bfloat162(hz, hw);
    l[2 * i]     = __nv_bfloat162(lx, ly);
    l[2 * i + 1] = __nv_bfloat162(lz, lw);
}

// ---------------------------------------------------------------------------
// 3-pass bf16 mma.sync GEMM: C[M,N] = A[M,K] @ B[N,K]^T, fp32 out.
// CTA tile 128x128, BK=64, double-buffered cp.async, SW128 swizzle.
// 256 threads = 8 warps (2 x 4); warp tile 64 x 32.
// Requires M%128==0, K%64==0. N handled with zero-fill + store guards.
// ---------------------------------------------------------------------------
#define GEMM_SMEM (2 * 4 * 128 * 128)

__global__ __launch_bounds__(256) void gemm3m(
    const __nv_bfloat16* __restrict__ Ah, const __nv_bfloat16* __restrict__ Al,
    const __nv_bfloat16* __restrict__ Bh, const __nv_bfloat16* __restrict__ Bl,
    float* __restrict__ C, int M, int N, int K) {
    extern __shared__ __align__(1024) char smem[];
    const uint32_t sb = smem_u32(smem);
    const int tid = threadIdx.x;
    const int lane = tid & 31;
    const int wid = tid >> 5;
    const int wr = wid >> 2, wc = wid & 3;
    const int m0 = blockIdx.y * 128, n0 = blockIdx.x * 128;

    constexpr int TILE = 128 * 128;        // bytes per operand tile
    constexpr int STAGE = 4 * TILE;        // Ah, Al, Bh, Bl

    const int nk = K >> 6;

    auto load_stage = [&](int kc, int s) {
        uint32_t base = sb + s * STAGE;
        int k0 = kc * 64;
        for (int e = tid; e < 4096; e += 256) {
            int t = e >> 10, r = (e >> 3) & 127, c = e & 7;
            uint32_t dst = base + t * TILE + sw128((uint32_t)(r * 128 + c * 16));
            if (t == 0) {
                cp16(dst, Ah + (size_t)(m0 + r) * K + k0 + c * 8);
            } else if (t == 1) {
                cp16(dst, Al + (size_t)(m0 + r) * K + k0 + c * 8);
            } else if (t == 2) {
                bool v = (n0 + r) < N;
                cp16z(dst, Bh + (size_t)(v ? (n0 + r) : 0) * K + k0 + c * 8, v);
            } else {
                bool v = (n0 + r) < N;
                cp16z(dst, Bl + (size_t)(v ? (n0 + r) : 0) * K + k0 + c * 8, v);
            }
        }
        asm volatile("cp.async.commit_group;" ::: "memory");
    };

    float acc[4][4][4];
#pragma unroll
    for (int mi = 0; mi < 4; mi++)
#pragma unroll
        for (int ni = 0; ni < 4; ni++)
#pragma unroll
            for (int j = 0; j < 4; j++) acc[mi][ni][j] = 0.0f;

    load_stage(0, 0);

    const int l16 = lane & 15;
    for (int kc = 0; kc < nk; kc++) {
        if (kc + 1 < nk) {
            load_stage(kc + 1, (kc + 1) & 1);
            asm volatile("cp.async.wait_group 1;" ::: "memory");
        } else {
            asm volatile("cp.async.wait_group 0;" ::: "memory");
        }
        __syncthreads();

        uint32_t base = sb + (kc & 1) * STAGE;
#pragma unroll
        for (int s = 0; s < 4; s++) {
            const int ksb = s * 32;  // k16 step -> bytes within row
            // A fragments (hi & lo)
            uint32_t ah[4][4], al[4][4];
            uint32_t aintra = (uint32_t)(ksb + (lane >> 4) * 16);
#pragma unroll
            for (int mi = 0; mi < 4; mi++) {
                uint32_t off = (uint32_t)((wr * 64 + mi * 16 + l16) * 128) + aintra;
                ldsm4(ah[mi], base + 0 * TILE + sw128(off));
                ldsm4(al[mi], base + 1 * TILE + sw128(off));
            }
            // B fragments (hi & lo)
            uint32_t bh[4][2], bl[4][2];
            uint32_t bintra = (uint32_t)(ksb + (l16 >> 3) * 16);
#pragma unroll
            for (int ni = 0; ni < 4; ni++) {
                uint32_t off = (uint32_t)((wc * 32 + ni * 8 + (l16 & 7)) * 128) + bintra;
                ldsm2(bh[ni], base + 2 * TILE + sw128(off));
                ldsm2(bl[ni], base + 3 * TILE + sw128(off));
            }
#pragma unroll
            for (int mi = 0; mi < 4; mi++)
#pragma unroll
                for (int ni = 0; ni < 4; ni++) {
                    mma16816(acc[mi][ni], ah[mi], bh[ni]);
                    mma16816(acc[mi][ni], ah[mi], bl[ni]);
                    mma16816(acc[mi][ni], al[mi], bh[ni]);
                }
        }
        __syncthreads();
    }

    // epilogue
#pragma unroll
    for (int mi = 0; mi < 4; mi++) {
        int row = m0 + wr * 64 + mi * 16 + (lane >> 2);
#pragma unroll
        for (int ni = 0; ni < 4; ni++) {
            int col = n0 + wc * 32 + ni * 8 + (lane & 3) * 2;
            if (col < N) {
                *(float2*)&C[(size_t)row * N + col] = make_float2(acc[mi][ni][0], acc[mi][ni][1]);
                *(float2*)&C[(size_t)(row + 8) * N + col] = make_float2(acc[mi][ni][2], acc[mi][ni][3]);
            }
        }
    }
}

// ---------------------------------------------------------------------------
// Pack Q / K
// ---------------------------------------------------------------------------
__global__ void pack_q_kernel(const float* __restrict__ qfull, float* __restrict__ Q) {
    long idx = (long)blockIdx.x * blockDim.x + threadIdx.x;
    int i = (int)(idx & 63);
    long t = idx >> 6;
    int s = (int)(t & (SS - 1));
    t >>= 11;
    int h = (int)(t & (HH - 1));
    int b = (int)(t >> 4);
    const float scale = 0.08838834764831845f;
    const float* src = qfull + ((size_t)(b * SS + s)) * DD + h * HDD;
    float* dst = Q + (((size_t)(b * HH + h) * SS + s)) * HDD;
    if (i < 32) {
        dst[2 * i]     = src[2 * i] * scale;
        dst[2 * i + 1] = src[2 * i + 1] * scale;
    } else {
        int j = i - 32;
        float x0 = src[64 + 2 * j], x1 = src[64 + 2 * j + 1];
        float ang = (float)s * c_freqs[j];
        float sn, cs;
        sincosf(ang, &sn, &cs);
        dst[64 + 2 * j]     = (x0 * cs - x1 * sn) * scale;
        dst[64 + 2 * j + 1] = (x1 * cs + x0 * sn) * scale;
    }
}

__global__ void pack_k_kernel(const float* __restrict__ knope,
                              const float* __restrict__ krope,
                              float* __restrict__ K) {
    long idx = (long)blockIdx.x * blockDim.x + threadIdx.x;
    int i = (int)(idx & 63);
    long t = idx >> 6;
    int s = (int)(t & (SS - 1));
    t >>= 11;
    int h = (int)(t & (HH - 1));
    int b = (int)(t >> 4);
    float* dst = K + (((size_t)(b * HH + h) * SS + s)) * HDD;
    if (i < 32) {
        const float* src = knope + ((size_t)(b * SS + s)) * (HH * NDD) + h * NDD;
        dst[2 * i]     = src[2 * i];
        dst[2 * i + 1] = src[2 * i + 1];
    } else {
        int j = i - 32;
        const float* src = krope + ((size_t)(b * SS + s)) * 64;
        float x0 = src[2 * j], x1 = src[2 * j + 1];
        float ang = (float)s * c_freqs[j];
        float sn, cs;
        sincosf(ang, &sn, &cs);
        dst[64 + 2 * j]     = x0 * cs - x1 * sn;
        dst[64 + 2 * j + 1] = x1 * cs + x0 * sn;
    }
}

// ---------------------------------------------------------------------------
// Flash attention (fp32, causal) — unchanged
// ---------------------------------------------------------------------------
#define FA_SMEM ((3 * 64 * 132 + 64 * 68) * 4)

__global__ __launch_bounds__(256) void fa_kernel(const float* __restrict__ Qp,
                                                 const float* __restrict__ Kp,
                                                 const float* __restrict__ Vf,
                                                 float* __restrict__ Oo) {
    extern __shared__ float sm[];
    float* Qs = sm;
    float* Ks = Qs + 64 * 132;
    float* Vs = Ks + 64 * 132;
    float* Ps = Vs + 64 * 132;

    const int tid = threadIdx.x;
    const int tx = tid & 15, ty = tid >> 4;
    const int bh = blockIdx.y;
    const int b = bh >> 4, h = bh & 15;
    const int qt = blockIdx.x;
    const int q0 = qt * 64;

    const float* Qbase = Qp + ((size_t)bh * SS + q0) * HDD;
    for (int e = tid; e < 64 * 32; e += 256) {
        int r = e >> 5, c4 = (e & 31) << 2;
        *(float4*)(Qs + r * 132 + c4) = *(const float4*)(Qbase + r * HDD + c4);
    }

    float m_i[4], l_i[4], O[4][8];
#pragma unroll
    for (int i = 0; i < 4; i++) {
        m_i[i] = -1e30f;
        l_i[i] = 0.0f;
#pragma unroll
        for (int j = 0; j < 8; j++) O[i][j] = 0.0f;
    }

    for (int nt = 0; nt <= qt; nt++) {
        const int n0 = nt * 64;
        const float* Kbase = Kp + ((size_t)bh * SS + n0) * HDD;
        for (int e = tid; e < 64 * 32; e += 256) {
            int r = e >> 5, c4 = (e & 31) << 2;
            *(float4*)(Ks + r * 132 + c4) = *(const float4*)(Kbase + r * HDD + c4);
            *(float4*)(Vs + r * 132 + c4) =
                *(const float4*)(Vf + ((size_t)(b * SS + n0 + r)) * DD + h * HDD + c4);
        }
        __syncthreads();

        float acc[4][4];
#pragma unroll
        for (int i = 0; i < 4; i++)
#pragma unroll
            for (int j = 0; j < 4; j++) acc[i][j] = 0.0f;

        for (int d4 = 0; d4 < 32; d4++) {
            float4 q4[4], k4[4];
#pragma unroll
            for (int i = 0; i < 4; i++) q4[i] = *(const float4*)(Qs + (ty * 4 + i) * 132 + d4 * 4);
#pragma unroll
            for (int j = 0; j < 4; j++) k4[j] = *(const float4*)(Ks + (tx + 16 * j) * 132 + d4 * 4);
#pragma unroll
            for (int i = 0; i < 4; i++)
#pragma unroll
                for (int j = 0; j < 4; j++) {
                    acc[i][j] = fmaf(q4[i].x, k4[j].x, acc[i][j]);
                    acc[i][j] = fmaf(q4[i].y, k4[j].y, acc[i][j]);
                    acc[i][j] = fmaf(q4[i].z, k4[j].z, acc[i][j]);
                    acc[i][j] = fmaf(q4[i].w, k4[j].w, acc[i][j]);
                }
        }

        if (nt == qt) {
#pragma unroll
            for (int i = 0; i < 4; i++)
#pragma unroll
                for (int j = 0; j < 4; j++)
                    if (n0 + tx + 16 * j > q0 + ty * 4 + i) acc[i][j] = -1e30f;
        }

#pragma unroll
        for (int i = 0; i < 4; i++) {
            float mx = fmaxf(fmaxf(acc[i][0], acc[i][1]), fmaxf(acc[i][2], acc[i][3]));
#pragma unroll
            for (int o = 8; o >= 1; o >>= 1) mx = fmaxf(mx, __shfl_xor_sync(0xffffffffu, mx, o, 16));
            float mnew = fmaxf(m_i[i], mx);
            float corr = __expf(m_i[i] - mnew);
            float rs = 0.0f;
#pragma unroll
            for (int j = 0; j < 4; j++) {
                float p = __expf(acc[i][j] - mnew);
                acc[i][j] = p;
                rs += p;
            }
#pragma unroll
            for (int o = 8; o >= 1; o >>= 1) rs += __shfl_xor_sync(0xffffffffu, rs, o, 16);
            l_i[i] = l_i[i] * corr + rs;
            m_i[i] = mnew;
#pragma unroll
            for (int j = 0; j < 8; j++) O[i][j] *= corr;
#pragma unroll
            for (int j = 0; j < 4; j++) Ps[(ty * 4 + i) * 68 + tx + 16 * j] = acc[i][j];
        }
        __syncthreads();

        for (int c = 0; c < 64; c++) {
            float p0 = Ps[(ty * 4 + 0) * 68 + c];
            float p1 = Ps[(ty * 4 + 1) * 68 + c];
            float p2 = Ps[(ty * 4 + 2) * 68 + c];
            float p3 = Ps[(ty * 4 + 3) * 68 + c];
            float4 v0 = *(const float4*)(Vs + c * 132 + tx * 8);
            float4 v1 = *(const float4*)(Vs + c * 132 + tx * 8 + 4);
            float vv[8] = {v0.x, v0.y, v0.z, v0.w, v1.x, v1.y, v1.z, v1.w};
#pragma unroll
            for (int j = 0; j < 8; j++) {
                O[0][j] = fmaf(p0, vv[j], O[0][j]);
                O[1][j] = fmaf(p1, vv[j], O[1][j]);
                O[2][j] = fmaf(p2, vv[j], O[2][j]);
                O[3][j] = fmaf(p3, vv[j], O[3][j]);
            }
        }
        __syncthreads();
    }

#pragma unroll
    for (int i = 0; i < 4; i++) {
        float inv = 1.0f / l_i[i];
        int row = q0 + ty * 4 + i;
        float* dst = Oo + ((size_t)(b * SS + row)) * DD + h * HDD + tx * 8;
        *(float4*)(dst)     = make_float4(O[i][0] * inv, O[i][1] * inv, O[i][2] * inv, O[i][3] * inv);
        *(float4*)(dst + 4) = make_float4(O[i][4] * inv, O[i][5] * inv, O[i][6] * inv, O[i][7] * inv);
    }
}

// ---------------------------------------------------------------------------
// Launch
// ---------------------------------------------------------------------------
static void run_split(const float* s, __nv_bfloat16* h, __nv_bfloat16* l, int n) {
    int n4 = n / 4;
    split_kernel<<<(n4 + 255) / 256, 256>>>((const float4*)s, (__nv_bfloat162*)h,
                                            (__nv_bfloat162*)l, n4);
}

extern "C" void kernel_launch(void* const* d_in, const int* in_sizes, int n_in,
                              void* d_out, int out_size) {
    const float* x         = (const float*)d_in[0];
    const float* wq        = (const float*)d_in[1];
    const float* w_kv_down = (const float*)d_in[2];
    const float* w_k_up    = (const float*)d_in[3];
    const float* w_k_rope  = (const float*)d_in[4];
    const float* w_v_up    = (const float*)d_in[5];
    const float* wo        = (const float*)d_in[6];
    float* out = (float*)d_out;

    float *qfull, *ckv, *knope, *krope, *vflat, *Q, *K, *attn;
    cudaGetSymbolAddress((void**)&qfull, g_qfull);
    cudaGetSymbolAddress((void**)&ckv,   g_ckv);
    cudaGetSymbolAddress((void**)&knope, g_knope);
    cudaGetSymbolAddress((void**)&krope, g_krope);
    cudaGetSymbolAddress((void**)&vflat, g_vflat);
    cudaGetSymbolAddress((void**)&Q,     g_Q);
    cudaGetSymbolAddress((void**)&K,     g_K);
    cudaGetSymbolAddress((void**)&attn,  g_attn);

    __nv_bfloat16 *xh, *xl, *wqh, *wql, *wkvh, *wkvl, *wkuph, *wkupl;
    __nv_bfloat16 *wkrh, *wkrl, *wvuph, *wvupl, *woh, *wol, *ckvh, *ckvl, *ath, *atl;
    cudaGetSymbolAddress((void**)&xh, g_xh);       cudaGetSymbolAddress((void**)&xl, g_xl);
    cudaGetSymbolAddress((void**)&wqh, g_wqh);     cudaGetSymbolAddress((void**)&wql, g_wql);
    cudaGetSymbolAddress((void**)&wkvh, g_wkvh);   cudaGetSymbolAddress((void**)&wkvl, g_wkvl);
    cudaGetSymbolAddress((void**)&wkuph, g_wkuph); cudaGetSymbolAddress((void**)&wkupl, g_wkupl);
    cudaGetSymbolAddress((void**)&wkrh, g_wkrh);   cudaGetSymbolAddress((void**)&wkrl, g_wkrl);
    cudaGetSymbolAddress((void**)&wvuph, g_wvuph); cudaGetSymbolAddress((void**)&wvupl, g_wvupl);
    cudaGetSymbolAddress((void**)&woh, g_woh);     cudaGetSymbolAddress((void**)&wol, g_wol);
    cudaGetSymbolAddress((void**)&ckvh, g_ckvh);   cudaGetSymbolAddress((void**)&ckvl, g_ckvl);
    cudaGetSymbolAddress((void**)&ath, g_ath);     cudaGetSymbolAddress((void**)&atl, g_atl);

    cudaFuncSetAttribute(gemm3m, cudaFuncAttributeMaxDynamicSharedMemorySize, GEMM_SMEM);
    cudaFuncSetAttribute(fa_kernel, cudaFuncAttributeMaxDynamicSharedMemorySize, FA_SMEM);

    const int M = BB * SS;  // 4096

    // split inputs + weights
    run_split(x,         xh,    xl,    BB * SS * DD);
    run_split(wq,        wqh,   wql,   DD * DD);
    run_split(w_kv_down, wkvh,  wkvl,  RR * DD);
    run_split(w_k_up,    wkuph, wkupl, HH * NDD * RR);
    run_split(w_k_rope,  wkrh,  wkrl,  64 * DD);
    run_split(w_v_up,    wvuph, wvupl, DD * RR);
    run_split(wo,        woh,   wol,   DD * DD);

    // q = x @ wq^T
    gemm3m<<<dim3(DD / 128, M / 128), 256, GEMM_SMEM>>>(xh, xl, wqh, wql, qfull, M, DD, DD);
    // c_kv = x @ w_kv_down^T
    gemm3m<<<dim3(RR / 128, M / 128), 256, GEMM_SMEM>>>(xh, xl, wkvh, wkvl, ckv, M, RR, DD);
    run_split(ckv, ckvh, ckvl, BB * SS * RR);
    // k_nope = ckv @ w_k_up^T
    gemm3m<<<dim3((HH * NDD) / 128, M / 128), 256, GEMM_SMEM>>>(ckvh, ckvl, wkuph, wkupl,
                                                                knope, M, HH * NDD, RR);
    // k_rope_raw = x @ w_k_rope^T  (N=64 -> zero-fill + guards)
    gemm3m<<<dim3(1, M / 128), 256, GEMM_SMEM>>>(xh, xl, wkrh, wkrl, krope, M, 64, DD);
    // v = ckv @ w_v_up^T
    gemm3m<<<dim3(DD / 128, M / 128), 256, GEMM_SMEM>>>(ckvh, ckvl, wvuph, wvupl, vflat, M, DD, RR);

    pack_q_kernel<<<(BB * HH * SS * 64) / 256, 256>>>(qfull, Q);
    pack_k_kernel<<<(BB * HH * SS * 64) / 256, 256>>>(knope, krope, K);

    fa_kernel<<<dim3(SS / 64, BB * HH), 256, FA_SMEM>>>(Q, K, vflat, attn);

    run_split(attn, ath, atl, BB * SS * DD);
    // out = attn @ wo^T
    gemm3m<<<dim3(DD / 128, M / 128), 256, GEMM_SMEM>>>(ath, atl, woh, wol, out, M, DD, DD);
}

// round 13
// speedup vs baseline: 1.0011x; 1.0010x over previous
#include <cuda_runtime.h>
#include <cuda_bf16.h>
#include <stdint.h>
#include <math.h>

// Problem constants
#define BB 2
#define SS 2048
#define DD 2048
#define HH 16
#define HDD 128
#define NDD 64
#define RR 512

// ---------------------------------------------------------------------------
// Scratch (device globals: no allocations allowed)
// ---------------------------------------------------------------------------
__device__ float g_qfull[BB * SS * DD];
__device__ float g_ckv[BB * SS * RR];
__device__ float g_knope[BB * SS * HH * NDD];
__device__ float g_krope[BB * SS * 64];
__device__ float g_vflat[BB * SS * DD];
__device__ float g_Q[BB * HH * SS * HDD];
__device__ float g_K[BB * HH * SS * HDD];
__device__ float g_attn[BB * SS * DD];

// bf16 hi/lo split buffers
__device__ __nv_bfloat16 g_xh[BB * SS * DD],  g_xl[BB * SS * DD];
__device__ __nv_bfloat16 g_wqh[DD * DD],      g_wql[DD * DD];
__device__ __nv_bfloat16 g_wkvh[RR * DD],     g_wkvl[RR * DD];
__device__ __nv_bfloat16 g_wkuph[HH * NDD * RR], g_wkupl[HH * NDD * RR];
__device__ __nv_bfloat16 g_wkrh[64 * DD],     g_wkrl[64 * DD];
__device__ __nv_bfloat16 g_wvuph[DD * RR],    g_wvupl[DD * RR];
__device__ __nv_bfloat16 g_woh[DD * DD],      g_wol[DD * DD];
__device__ __nv_bfloat16 g_ckvh[BB * SS * RR], g_ckvl[BB * SS * RR];
__device__ __nv_bfloat16 g_ath[BB * SS * DD],  g_atl[BB * SS * DD];

__constant__ float c_freqs[32] = {
    1.0f, 0.7498942093324559f, 0.5623413251903491f, 0.42169650342858224f,
    0.31622776601683794f, 0.23713737056616552f, 0.17782794100389228f, 0.13335214321633237f,
    0.1f, 0.07498942093324558f, 0.05623413251903491f, 0.042169650342858224f,
    0.03162277660168379f, 0.023713737056616554f, 0.01778279410038923f, 0.013335214321633237f,
    0.01f, 0.007498942093324559f, 0.005623413251903491f, 0.004216965034285822f,
    0.0031622776601683794f, 0.0023713737056616554f, 0.0017782794100389228f, 0.0013335214321633237f,
    0.001f, 0.0007498942093324559f, 0.0005623413251903491f, 0.00042169650342858224f,
    0.00031622776601683794f, 0.00023713737056616554f, 0.00017782794100389228f, 0.00013335214321633237f};

// ---------------------------------------------------------------------------
// PTX helpers (sm_80-era ISA only — tcgen05 is NOT available: harness ptxas
// target is sm_103 without the 'a' feature suffix)
// ---------------------------------------------------------------------------
__device__ __forceinline__ uint32_t smem_u32(const void* p) {
    uint32_t a;
    asm("{ .reg .u64 t; cvta.to.shared.u64 t, %1; cvt.u32.u64 %0, t; }" : "=r"(a) : "l"(p));
    return a;
}
__device__ __forceinline__ uint32_t sw128(uint32_t o) { return o ^ ((o >> 3) & 0x70); }

__device__ __forceinline__ void cp16(uint32_t smem_dst, const void* gsrc) {
    asm volatile("cp.async.cg.shared.global [%0], [%1], 16;" :: "r"(smem_dst), "l"(gsrc));
}
__device__ __forceinline__ void cp16z(uint32_t smem_dst, const void* gsrc, bool valid) {
    int sz = valid ? 16 : 0;
    asm volatile("cp.async.cg.shared.global [%0], [%1], 16, %2;"
                 :: "r"(smem_dst), "l"(gsrc), "r"(sz));
}
__device__ __forceinline__ void ldsm4(uint32_t* r, uint32_t addr) {
    asm volatile("ldmatrix.sync.aligned.m8n8.x4.shared.b16 {%0,%1,%2,%3}, [%4];"
                 : "=r"(r[0]), "=r"(r[1]), "=r"(r[2]), "=r"(r[3]) : "r"(addr));
}
__device__ __forceinline__ void ldsm2(uint32_t* r, uint32_t addr) {
    asm volatile("ldmatrix.sync.aligned.m8n8.x2.shared.b16 {%0,%1}, [%2];"
                 : "=r"(r[0]), "=r"(r[1]) : "r"(addr));
}
__device__ __forceinline__ void mma16816(float* c, const uint32_t* a, const uint32_t* b) {
    asm volatile(
        "mma.sync.aligned.m16n8k16.row.col.f32.bf16.bf16.f32 "
        "{%0,%1,%2,%3}, {%4,%5,%6,%7}, {%8,%9}, {%0,%1,%2,%3};"
        : "+f"(c[0]), "+f"(c[1]), "+f"(c[2]), "+f"(c[3])
        : "r"(a[0]), "r"(a[1]), "r"(a[2]), "r"(a[3]), "r"(b[0]), "r"(b[1]));
}

// ---------------------------------------------------------------------------
// split fp32 -> bf16 hi + bf16 lo
// ---------------------------------------------------------------------------
__global__ void split_kernel(const float4* __restrict__ s, __nv_bfloat162* __restrict__ h,
                             __nv_bfloat162* __restrict__ l, int n4) {
    int i = blockIdx.x * blockDim.x + threadIdx.x;
    if (i >= n4) return;
    float4 v = s[i];
    __nv_bfloat16 hx = __float2bfloat16(v.x), hy = __float2bfloat16(v.y);
    __nv_bfloat16 hz = __float2bfloat16(v.z), hw = __float2bfloat16(v.w);
    __nv_bfloat16 lx = __float2bfloat16(v.x - __bfloat162float(hx));
    __nv_bfloat16 ly = __float2bfloat16(v.y - __bfloat162float(hy));
    __nv_bfloat16 lz = __float2bfloat16(v.z - __bfloat162float(hz));
    __nv_bfloat16 lw = __float2bfloat16(v.w - __bfloat162float(hw));
    h[2 * i]     = __nv_bfloat162(hx, hy);
    h[2 * i + 1] = __nv_bfloat162(hz, hw);
    l[2 * i]     = __nv_bfloat162(lx, ly);
    l[2 * i + 1] = __nv_bfloat162(lz, lw);
}

// ---------------------------------------------------------------------------
// 3-pass bf16 mma.sync GEMM: C[M,N] = A[M,K] @ B[N,K]^T, fp32 out.
// CTA tile 128x128, BK=64, double-buffered cp.async, SW128 swizzle.
// 256 threads = 8 warps (2 x 4); warp tile 64 x 32.
// Requires M%128==0, K%64==0. N handled with zero-fill + store guards.
// ---------------------------------------------------------------------------
#define GEMM_SMEM (2 * 4 * 128 * 128)

__global__ __launch_bounds__(256) void gemm3m(
    const __nv_bfloat16* __restrict__ Ah, const __nv_bfloat16* __restrict__ Al,
    const __nv_bfloat16* __restrict__ Bh, const __nv_bfloat16* __restrict__ Bl,
    float* __restrict__ C, int M, int N, int K) {
    extern __shared__ __align__(1024) char smem[];
    const uint32_t sb = smem_u32(smem);
    const int tid = threadIdx.x;
    const int lane = tid & 31;
    const int wid = tid >> 5;
    const int wr = wid >> 2, wc = wid & 3;
    const int m0 = blockIdx.y * 128, n0 = blockIdx.x * 128;

    constexpr int TILE = 128 * 128;        // bytes per operand tile
    constexpr int STAGE = 4 * TILE;        // Ah, Al, Bh, Bl

    const int nk = K >> 6;

    auto load_stage = [&](int kc, int s) {
        uint32_t base = sb + s * STAGE;
        int k0 = kc * 64;
        for (int e = tid; e < 4096; e += 256) {
            int t = e >> 10, r = (e >> 3) & 127, c = e & 7;
            uint32_t dst = base + t * TILE + sw128((uint32_t)(r * 128 + c * 16));
            if (t == 0) {
                cp16(dst, Ah + (size_t)(m0 + r) * K + k0 + c * 8);
            } else if (t == 1) {
                cp16(dst, Al + (size_t)(m0 + r) * K + k0 + c * 8);
            } else if (t == 2) {
                bool v = (n0 + r) < N;
                cp16z(dst, Bh + (size_t)(v ? (n0 + r) : 0) * K + k0 + c * 8, v);
            } else {
                bool v = (n0 + r) < N;
                cp16z(dst, Bl + (size_t)(v ? (n0 + r) : 0) * K + k0 + c * 8, v);
            }
        }
        asm volatile("cp.async.commit_group;" ::: "memory");
    };

    float acc[4][4][4];
#pragma unroll
    for (int mi = 0; mi < 4; mi++)
#pragma unroll
        for (int ni = 0; ni < 4; ni++)
#pragma unroll
            for (int j = 0; j < 4; j++) acc[mi][ni][j] = 0.0f;

    load_stage(0, 0);

    const int l16 = lane & 15;
    for (int kc = 0; kc < nk; kc++) {
        if (kc + 1 < nk) {
            load_stage(kc + 1, (kc + 1) & 1);
            asm volatile("cp.async.wait_group 1;" ::: "memory");
        } else {
            asm volatile("cp.async.wait_group 0;" ::: "memory");
        }
        __syncthreads();

        uint32_t base = sb + (kc & 1) * STAGE;
#pragma unroll
        for (int s = 0; s < 4; s++) {
            const int ksb = s * 32;  // k16 step -> bytes within row
            // A fragments (hi & lo)
            uint32_t ah[4][4], al[4][4];
            uint32_t aintra = (uint32_t)(ksb + (lane >> 4) * 16);
#pragma unroll
            for (int mi = 0; mi < 4; mi++) {
                uint32_t off = (uint32_t)((wr * 64 + mi * 16 + l16) * 128) + aintra;
                ldsm4(ah[mi], base + 0 * TILE + sw128(off));
                ldsm4(al[mi], base + 1 * TILE + sw128(off));
            }
            // B fragments (hi & lo)
            uint32_t bh[4][2], bl[4][2];
            uint32_t bintra = (uint32_t)(ksb + (l16 >> 3) * 16);
#pragma unroll
            for (int ni = 0; ni < 4; ni++) {
                uint32_t off = (uint32_t)((wc * 32 + ni * 8 + (l16 & 7)) * 128) + bintra;
                ldsm2(bh[ni], base + 2 * TILE + sw128(off));
                ldsm2(bl[ni], base + 3 * TILE + sw128(off));
            }
#pragma unroll
            for (int mi = 0; mi < 4; mi++)
#pragma unroll
                for (int ni = 0; ni < 4; ni++) {
                    mma16816(acc[mi][ni], ah[mi], bh[ni]);
                    mma16816(acc[mi][ni], ah[mi], bl[ni]);
                    mma16816(acc[mi][ni], al[mi], bh[ni]);
                }
        }
        __syncthreads();
    }

    // epilogue
#pragma unroll
    for (int mi = 0; mi < 4; mi++) {
        int row = m0 + wr * 64 + mi * 16 + (lane >> 2);
#pragma unroll
        for (int ni = 0; ni < 4; ni++) {
            int col = n0 + wc * 32 + ni * 8 + (lane & 3) * 2;
            if (col < N) {
                *(float2*)&C[(size_t)row * N + col] = make_float2(acc[mi][ni][0], acc[mi][ni][1]);
                *(float2*)&C[(size_t)(row + 8) * N + col] = make_float2(acc[mi][ni][2], acc[mi][ni][3]);
            }
        }
    }
}

// ---------------------------------------------------------------------------
// Pack Q / K
// ---------------------------------------------------------------------------
__global__ void pack_q_kernel(const float* __restrict__ qfull, float* __restrict__ Q) {
    long idx = (long)blockIdx.x * blockDim.x + threadIdx.x;
    int i = (int)(idx & 63);
    long t = idx >> 6;
    int s = (int)(t & (SS - 1));
    t >>= 11;
    int h = (int)(t & (HH - 1));
    int b = (int)(t >> 4);
    const float scale = 0.08838834764831845f;
    const float* src = qfull + ((size_t)(b * SS + s)) * DD + h * HDD;
    float* dst = Q + (((size_t)(b * HH + h) * SS + s)) * HDD;
    if (i < 32) {
        dst[2 * i]     = src[2 * i] * scale;
        dst[2 * i + 1] = src[2 * i + 1] * scale;
    } else {
        int j = i - 32;
        float x0 = src[64 + 2 * j], x1 = src[64 + 2 * j + 1];
        float ang = (float)s * c_freqs[j];
        float sn, cs;
        sincosf(ang, &sn, &cs);
        dst[64 + 2 * j]     = (x0 * cs - x1 * sn) * scale;
        dst[64 + 2 * j + 1] = (x1 * cs + x0 * sn) * scale;
    }
}

__global__ void pack_k_kernel(const float* __restrict__ knope,
                              const float* __restrict__ krope,
                              float* __restrict__ K) {
    long idx = (long)blockIdx.x * blockDim.x + threadIdx.x;
    int i = (int)(idx & 63);
    long t = idx >> 6;
    int s = (int)(t & (SS - 1));
    t >>= 11;
    int h = (int)(t & (HH - 1));
    int b = (int)(t >> 4);
    float* dst = K + (((size_t)(b * HH + h) * SS + s)) * HDD;
    if (i < 32) {
        const float* src = knope + ((size_t)(b * SS + s)) * (HH * NDD) + h * NDD;
        dst[2 * i]     = src[2 * i];
        dst[2 * i + 1] = src[2 * i + 1];
    } else {
        int j = i - 32;
        const float* src = krope + ((size_t)(b * SS + s)) * 64;
        float x0 = src[2 * j], x1 = src[2 * j + 1];
        float ang = (float)s * c_freqs[j];
        float sn, cs;
        sincosf(ang, &sn, &cs);
        dst[64 + 2 * j]     = x0 * cs - x1 * sn;
        dst[64 + 2 * j + 1] = x1 * cs + x0 * sn;
    }
}

// ---------------------------------------------------------------------------
// Flash attention (fp32, causal) — unchanged
// ---------------------------------------------------------------------------
#define FA_SMEM ((3 * 64 * 132 + 64 * 68) * 4)

__global__ __launch_bounds__(256) void fa_kernel(const float* __restrict__ Qp,
                                                 const float* __restrict__ Kp,
                                                 const float* __restrict__ Vf,
                                                 float* __restrict__ Oo) {
    extern __shared__ float sm[];
    float* Qs = sm;
    float* Ks = Qs + 64 * 132;
    float* Vs = Ks + 64 * 132;
    float* Ps = Vs + 64 * 132;

    const int tid = threadIdx.x;
    const int tx = tid & 15, ty = tid >> 4;
    const int bh = blockIdx.y;
    const int b = bh >> 4, h = bh & 15;
    const int qt = blockIdx.x;
    const int q0 = qt * 64;

    const float* Qbase = Qp + ((size_t)bh * SS + q0) * HDD;
    for (int e = tid; e < 64 * 32; e += 256) {
        int r = e >> 5, c4 = (e & 31) << 2;
        *(float4*)(Qs + r * 132 + c4) = *(const float4*)(Qbase + r * HDD + c4);
    }

    float m_i[4], l_i[4], O[4][8];
#pragma unroll
    for (int i = 0; i < 4; i++) {
        m_i[i] = -1e30f;
        l_i[i] = 0.0f;
#pragma unroll
        for (int j = 0; j < 8; j++) O[i][j] = 0.0f;
    }

    for (int nt = 0; nt <= qt; nt++) {
        const int n0 = nt * 64;
        const float* Kbase = Kp + ((size_t)bh * SS + n0) * HDD;
        for (int e = tid; e < 64 * 32; e += 256) {
            int r = e >> 5, c4 = (e & 31) << 2;
            *(float4*)(Ks + r * 132 + c4) = *(const float4*)(Kbase + r * HDD + c4);
            *(float4*)(Vs + r * 132 + c4) =
                *(const float4*)(Vf + ((size_t)(b * SS + n0 + r)) * DD + h * HDD + c4);
        }
        __syncthreads();

        float acc[4][4];
#pragma unroll
        for (int i = 0; i < 4; i++)
#pragma unroll
            for (int j = 0; j < 4; j++) acc[i][j] = 0.0f;

        for (int d4 = 0; d4 < 32; d4++) {
            float4 q4[4], k4[4];
#pragma unroll
            for (int i = 0; i < 4; i++) q4[i] = *(const float4*)(Qs + (ty * 4 + i) * 132 + d4 * 4);
#pragma unroll
            for (int j = 0; j < 4; j++) k4[j] = *(const float4*)(Ks + (tx + 16 * j) * 132 + d4 * 4);
#pragma unroll
            for (int i = 0; i < 4; i++)
#pragma unroll
                for (int j = 0; j < 4; j++) {
                    acc[i][j] = fmaf(q4[i].x, k4[j].x, acc[i][j]);
                    acc[i][j] = fmaf(q4[i].y, k4[j].y, acc[i][j]);
                    acc[i][j] = fmaf(q4[i].z, k4[j].z, acc[i][j]);
                    acc[i][j] = fmaf(q4[i].w, k4[j].w, acc[i][j]);
                }
        }

        if (nt == qt) {
#pragma unroll
            for (int i = 0; i < 4; i++)
#pragma unroll
                for (int j = 0; j < 4; j++)
                    if (n0 + tx + 16 * j > q0 + ty * 4 + i) acc[i][j] = -1e30f;
        }

#pragma unroll
        for (int i = 0; i < 4; i++) {
            float mx = fmaxf(fmaxf(acc[i][0], acc[i][1]), fmaxf(acc[i][2], acc[i][3]));
#pragma unroll
            for (int o = 8; o >= 1; o >>= 1) mx = fmaxf(mx, __shfl_xor_sync(0xffffffffu, mx, o, 16));
            float mnew = fmaxf(m_i[i], mx);
            float corr = __expf(m_i[i] - mnew);
            float rs = 0.0f;
#pragma unroll
            for (int j = 0; j < 4; j++) {
                float p = __expf(acc[i][j] - mnew);
                acc[i][j] = p;
                rs += p;
            }
#pragma unroll
            for (int o = 8; o >= 1; o >>= 1) rs += __shfl_xor_sync(0xffffffffu, rs, o, 16);
            l_i[i] = l_i[i] * corr + rs;
            m_i[i] = mnew;
#pragma unroll
            for (int j = 0; j < 8; j++) O[i][j] *= corr;
#pragma unroll
            for (int j = 0; j < 4; j++) Ps[(ty * 4 + i) * 68 + tx + 16 * j] = acc[i][j];
        }
        __syncthreads();

        for (int c = 0; c < 64; c++) {
            float p0 = Ps[(ty * 4 + 0) * 68 + c];
            float p1 = Ps[(ty * 4 + 1) * 68 + c];
            float p2 = Ps[(ty * 4 + 2) * 68 + c];
            float p3 = Ps[(ty * 4 + 3) * 68 + c];
            float4 v0 = *(const float4*)(Vs + c * 132 + tx * 8);
            float4 v1 = *(const float4*)(Vs + c * 132 + tx * 8 + 4);
            float vv[8] = {v0.x, v0.y, v0.z, v0.w, v1.x, v1.y, v1.z, v1.w};
#pragma unroll
            for (int j = 0; j < 8; j++) {
                O[0][j] = fmaf(p0, vv[j], O[0][j]);
                O[1][j] = fmaf(p1, vv[j], O[1][j]);
                O[2][j] = fmaf(p2, vv[j], O[2][j]);
                O[3][j] = fmaf(p3, vv[j], O[3][j]);
            }
        }
        __syncthreads();
    }

#pragma unroll
    for (int i = 0; i < 4; i++) {
        float inv = 1.0f / l_i[i];
        int row = q0 + ty * 4 + i;
        float* dst = Oo + ((size_t)(b * SS + row)) * DD + h * HDD + tx * 8;
        *(float4*)(dst)     = make_float4(O[i][0] * inv, O[i][1] * inv, O[i][2] * inv, O[i][3] * inv);
        *(float4*)(dst + 4) = make_float4(O[i][4] * inv, O[i][5] * inv, O[i][6] * inv, O[i][7] * inv);
    }
}

// ---------------------------------------------------------------------------
// Launch
// ---------------------------------------------------------------------------
static void run_split(const float* s, __nv_bfloat16* h, __nv_bfloat16* l, int n) {
    int n4 = n / 4;
    split_kernel<<<(n4 + 255) / 256, 256>>>((const float4*)s, (__nv_bfloat162*)h,
                                            (__nv_bfloat162*)l, n4);
}

extern "C" void kernel_launch(void* const* d_in, const int* in_sizes, int n_in,
                              void* d_out, int out_size) {
    const float* x         = (const float*)d_in[0];
    const float* wq        = (const float*)d_in[1];
    const float* w_kv_down = (const float*)d_in[2];
    const float* w_k_up    = (const float*)d_in[3];
    const float* w_k_rope  = (const float*)d_in[4];
    const float* w_v_up    = (const float*)d_in[5];
    const float* wo        = (const float*)d_in[6];
    float* out = (float*)d_out;

    float *qfull, *ckv, *knope, *krope, *vflat, *Q, *K, *attn;
    cudaGetSymbolAddress((void**)&qfull, g_qfull);
    cudaGetSymbolAddress((void**)&ckv,   g_ckv);
    cudaGetSymbolAddress((void**)&knope, g_knope);
    cudaGetSymbolAddress((void**)&krope, g_krope);
    cudaGetSymbolAddress((void**)&vflat, g_vflat);
    cudaGetSymbolAddress((void**)&Q,     g_Q);
    cudaGetSymbolAddress((void**)&K,     g_K);
    cudaGetSymbolAddress((void**)&attn,  g_attn);

    __nv_bfloat16 *xh, *xl, *wqh, *wql, *wkvh, *wkvl, *wkuph, *wkupl;
    __nv_bfloat16 *wkrh, *wkrl, *wvuph, *wvupl, *woh, *wol, *ckvh, *ckvl, *ath, *atl;
    cudaGetSymbolAddress((void**)&xh, g_xh);       cudaGetSymbolAddress((void**)&xl, g_xl);
    cudaGetSymbolAddress((void**)&wqh, g_wqh);     cudaGetSymbolAddress((void**)&wql, g_wql);
    cudaGetSymbolAddress((void**)&wkvh, g_wkvh);   cudaGetSymbolAddress((void**)&wkvl, g_wkvl);
    cudaGetSymbolAddress((void**)&wkuph, g_wkuph); cudaGetSymbolAddress((void**)&wkupl, g_wkupl);
    cudaGetSymbolAddress((void**)&wkrh, g_wkrh);   cudaGetSymbolAddress((void**)&wkrl, g_wkrl);
    cudaGetSymbolAddress((void**)&wvuph, g_wvuph); cudaGetSymbolAddress((void**)&wvupl, g_wvupl);
    cudaGetSymbolAddress((void**)&woh, g_woh);     cudaGetSymbolAddress((void**)&wol, g_wol);
    cudaGetSymbolAddress((void**)&ckvh, g_ckvh);   cudaGetSymbolAddress((void**)&ckvl, g_ckvl);
    cudaGetSymbolAddress((void**)&ath, g_ath);     cudaGetSymbolAddress((void**)&atl, g_atl);

    cudaFuncSetAttribute(gemm3m, cudaFuncAttributeMaxDynamicSharedMemorySize, GEMM_SMEM);
    cudaFuncSetAttribute(fa_kernel, cudaFuncAttributeMaxDynamicSharedMemorySize, FA_SMEM);

    const int M = BB * SS;  // 4096

    // split inputs + weights
    run_split(x,         xh,    xl,    BB * SS * DD);
    run_split(wq,        wqh,   wql,   DD * DD);
    run_split(w_kv_down, wkvh,  wkvl,  RR * DD);
    run_split(w_k_up,    wkuph, wkupl, HH * NDD * RR);
    run_split(w_k_rope,  wkrh,  wkrl,  64 * DD);
    run_split(w_v_up,    wvuph, wvupl, DD * RR);
    run_split(wo,        woh,   wol,   DD * DD);

    // q = x @ wq^T
    gemm3m<<<dim3(DD / 128, M / 128), 256, GEMM_SMEM>>>(xh, xl, wqh, wql, qfull, M, DD, DD);
    // c_kv = x @ w_kv_down^T
    gemm3m<<<dim3(RR / 128, M / 128), 256, GEMM_SMEM>>>(xh, xl, wkvh, wkvl, ckv, M, RR, DD);
    run_split(ckv, ckvh, ckvl, BB * SS * RR);
    // k_nope = ckv @ w_k_up^T
    gemm3m<<<dim3((HH * NDD) / 128, M / 128), 256, GEMM_SMEM>>>(ckvh, ckvl, wkuph, wkupl,
                                                                knope, M, HH * NDD, RR);
    // k_rope_raw = x @ w_k_rope^T  (N=64 -> zero-fill + guards)
    gemm3m<<<dim3(1, M / 128), 256, GEMM_SMEM>>>(xh, xl, wkrh, wkrl, krope, M, 64, DD);
    // v = ckv @ w_v_up^T
    gemm3m<<<dim3(DD / 128, M / 128), 256, GEMM_SMEM>>>(ckvh, ckvl, wvuph, wvupl, vflat, M, DD, RR);

    pack_q_kernel<<<(BB * HH * SS * 64) / 256, 256>>>(qfull, Q);
    pack_k_kernel<<<(BB * HH * SS * 64) / 256, 256>>>(knope, krope, K);

    fa_kernel<<<dim3(SS / 64, BB * HH), 256, FA_SMEM>>>(Q, K, vflat, attn);

    run_split(attn, ath, atl, BB * SS * DD);
    // out = attn @ wo^T
    gemm3m<<<dim3(DD / 128, M / 128), 256, GEMM_SMEM>>>(ath, atl, woh, wol, out, M, DD, DD);
}